// round 11
// baseline (speedup 1.0000x reference)
#include <cuda_runtime.h>
#include <math.h>

// DAGMixer R11: 4 rows per CTA (512 threads) — extend R10's dead-window
// amortization (R10: 2 rows, ncu 54.3us, DRAM 82.0%).
//   logits[row] = dot(orig[row], W[0:H]) + dot(dag[row], W[H:2H]) + b
//   gate = sigmoid(logits); mixed[row] = orig + gate*(dag - orig)
// rows = B*T = 16384 (divisible by 4), H = 2048 (fp32).
//
// Grid = rows/4 CTAs, 512 threads, 2 CTAs/SM (regs ~56). Thread t covers
// float4 index t of rows A..A+3. The reduce/BAR/sigmoid window is paid
// once per 64KB of traffic; W loaded once per 4 rows. The 4 gate-finalize
// chains run on 4 different warps (tid 0/32/64/96) in parallel.

#define THREADS 512
#define H_DIM   2048
#define F4_ROW  (H_DIM / 4)   // 512 float4 per row = 1 per thread
#define NWARP   (THREADS / 32)
#define ROWS_PER_CTA 4

__global__ __launch_bounds__(THREADS, 2)
void dagmixer_kernel(const float* __restrict__ orig,
                     const float* __restrict__ dag,
                     const float* __restrict__ w,     // [2H]: W_o then W_d
                     const float* __restrict__ bgate, // [1]
                     float* __restrict__ mixed,       // [rows*H]
                     float* __restrict__ gate_out)    // [rows]
{
    const int rowA = blockIdx.x * ROWS_PER_CTA;
    const int tid  = threadIdx.x;

    const float4* __restrict__ o0 = (const float4*)(orig + (size_t)rowA * H_DIM);
    const float4* __restrict__ d0 = (const float4*)(dag  + (size_t)rowA * H_DIM);

    // Row data: 8 float4 live across the barriers (32 floats).
    float4 ov[ROWS_PER_CTA], dv[ROWS_PER_CTA];
    #pragma unroll
    for (int r = 0; r < ROWS_PER_CTA; r++) {
        ov[r] = o0[r * F4_ROW + tid];
        dv[r] = d0[r * F4_ROW + tid];
    }

    // W loaded once per CTA (serves all 4 rows), consumed immediately.
    const float4 a = ((const float4*)w)[tid];
    const float4 c = ((const float4*)(w + H_DIM))[tid];

    float p[ROWS_PER_CTA];
    #pragma unroll
    for (int r = 0; r < ROWS_PER_CTA; r++) {
        p[r] = ov[r].x * a.x + ov[r].y * a.y + ov[r].z * a.z + ov[r].w * a.w
             + dv[r].x * c.x + dv[r].y * c.y + dv[r].z * c.z + dv[r].w * c.w;
    }

    // Warp reduce all 4 partials (interleaved shfl chains).
    #pragma unroll
    for (int off = 16; off > 0; off >>= 1) {
        #pragma unroll
        for (int r = 0; r < ROWS_PER_CTA; r++)
            p[r] += __shfl_xor_sync(0xffffffff, p[r], off);
    }

    __shared__ float ws[ROWS_PER_CTA][NWARP];
    __shared__ float gate_sh[ROWS_PER_CTA];
    const int wid  = tid >> 5;
    const int lane = tid & 31;
    if (lane == 0) {
        #pragma unroll
        for (int r = 0; r < ROWS_PER_CTA; r++) ws[r][wid] = p[r];
    }
    __syncthreads();

    // Gate r finalized by warp r (tid = 32*r) — 4 parallel serial chains.
    if (lane == 0 && wid < ROWS_PER_CTA) {
        const int r = wid;
        float s = bgate[0];
        #pragma unroll
        for (int i = 0; i < NWARP; i++) s += ws[r][i];
        const float g = 1.0f / (1.0f + __expf(-s));
        gate_sh[r] = g;
        gate_out[rowA + r] = g;
    }
    __syncthreads();

    float4* __restrict__ m0 = (float4*)(mixed + (size_t)rowA * H_DIM);
    #pragma unroll
    for (int r = 0; r < ROWS_PER_CTA; r++) {
        const float g = gate_sh[r];
        float4 out;
        out.x = ov[r].x + g * (dv[r].x - ov[r].x);
        out.y = ov[r].y + g * (dv[r].y - ov[r].y);
        out.z = ov[r].z + g * (dv[r].z - ov[r].z);
        out.w = ov[r].w + g * (dv[r].w - ov[r].w);
        m0[r * F4_ROW + tid] = out;
    }
}

extern "C" void kernel_launch(void* const* d_in, const int* in_sizes, int n_in,
                              void* d_out, int out_size)
{
    const float* orig  = (const float*)d_in[0];  // original_hidden [B,T,H]
    const float* dag   = (const float*)d_in[1];  // dag_hidden      [B,T,H]
    const float* wgate = (const float*)d_in[2];  // W_gate          [2H,1]
    const float* bgate = (const float*)d_in[3];  // b_gate          [1]

    const int total = in_sizes[0];               // B*T*H
    const int rows  = total / H_DIM;             // B*T (divisible by 4)

    float* mixed    = (float*)d_out;             // first B*T*H floats
    float* gate_out = (float*)d_out + total;     // then B*T gate values

    dagmixer_kernel<<<rows / ROWS_PER_CTA, THREADS>>>(orig, dag, wgate, bgate,
                                                      mixed, gate_out);
}